// round 8
// baseline (speedup 1.0000x reference)
#include <cuda_runtime.h>
#include <cuda_bf16.h>
#include <cstdint>

// ---------------------------------------------------------------------------
// IMCNN forward. HMMA m16n8k16 bf16, bf16x3 split, fp32 accum.
// R8: register-relief inner loop (al/bl share registers; peak live frags
//     64->48), split-K x3 on big conv layers (wave quant 1.18->1.045),
//     split-K x2 on layer 0.
// ---------------------------------------------------------------------------

#define V      6890
#define RR     5
#define AA     8
#define TT     100
#define NCONV  800
#define KPAD_BIG 4032
#define KPAD_S   128
#define EPS_BN 1e-3f

__device__ float g_x[V * TT];
__device__ float g_conv[3 * V * NCONV];        // up to 3 split-K partials
__device__ __align__(16) __nv_bfloat16 g_pa[(size_t)V * 2 * KPAD_BIG];
__device__ __align__(16) __nv_bfloat16 g_bb[(size_t)NCONV * 2 * KPAD_BIG];
__device__ __align__(16) __nv_bfloat16 g_xx[(size_t)V * 2 * KPAD_S];
__device__ __align__(16) __nv_bfloat16 g_dd[(size_t)V * 2 * KPAD_S];

// -------------------- PTX helpers --------------------
__device__ __forceinline__ uint32_t smem_u32(const void* p) {
    uint32_t a;
    asm("{ .reg .u64 t; cvta.to.shared.u64 t, %1; cvt.u32.u64 %0, t; }"
        : "=r"(a) : "l"(p));
    return a;
}
#define CP_ASYNC16(dst, src) \
    asm volatile("cp.async.cg.shared.global [%0], [%1], 16;" \
                 :: "r"(dst), "l"(src))
#define CP_COMMIT() asm volatile("cp.async.commit_group;" ::: "memory")
#define CP_WAIT1()  asm volatile("cp.async.wait_group 1;" ::: "memory")
#define CP_WAIT0()  asm volatile("cp.async.wait_group 0;" ::: "memory")

#define LDSM4(R, addr) \
    asm volatile("ldmatrix.sync.aligned.m8n8.x4.shared.b16 {%0,%1,%2,%3}, [%4];" \
        : "=r"((R)[0]), "=r"((R)[1]), "=r"((R)[2]), "=r"((R)[3]) : "r"(addr))

#define SWZ(o) ((o) ^ (((o) >> 3) & 0x70))

__device__ __forceinline__ void mma16816(float* c, const uint32_t* a,
                                         const uint32_t* b) {
    asm volatile(
        "mma.sync.aligned.m16n8k16.row.col.f32.bf16.bf16.f32 "
        "{%0,%1,%2,%3}, {%4,%5,%6,%7}, {%8,%9}, {%0,%1,%2,%3};"
        : "+f"(c[0]), "+f"(c[1]), "+f"(c[2]), "+f"(c[3])
        : "r"(a[0]), "r"(a[1]), "r"(a[2]), "r"(a[3]), "r"(b[0]), "r"(b[1]));
}

// -------------------- small kernels --------------------
__global__ void k_norm(const float* __restrict__ sig,
                       const float* __restrict__ mean,
                       const float* __restrict__ var) {
    int i = blockIdx.x * blockDim.x + threadIdx.x;
    if (i < V * 3) {
        int c = i % 3;
        g_x[i] = (sig[i] - mean[c]) / sqrtf(var[c]);
    }
}

__device__ __forceinline__ void store4(__nv_bfloat16* buf, size_t rowbase,
                                       int k0, const float* s) {
    int kb = k0 >> 4, pos = k0 & 15;
    __nv_bfloat16 hv[4], lv[4];
#pragma unroll
    for (int e = 0; e < 4; ++e) {
        hv[e] = __float2bfloat16_rn(s[e]);
        lv[e] = __float2bfloat16_rn(s[e] - __bfloat162float(hv[e]));
    }
    size_t base = rowbase + (size_t)(kb * 32 + pos);
    *(uint2*)(buf + base)      = *(const uint2*)hv;
    *(uint2*)(buf + base + 16) = *(const uint2*)lv;
}

template <int CIN, int KPAD>
__global__ void k_patch(const int* __restrict__ bc_idx,
                        const float* __restrict__ bc_w,
                        __nv_bfloat16* __restrict__ pa) {
    constexpr int QK = KPAD / 4;
    constexpr int K = RR * AA * CIN;
    int i = blockIdx.x * blockDim.x + threadIdx.x;
    if (i >= V * QK) return;
    int q = i % QK, v = i / QK;
    int k0 = q * 4;
    float s[4] = {0.f, 0.f, 0.f, 0.f};
    if (k0 < K) {
        if (CIN % 4 == 0) {
            int ra = k0 / CIN, c0 = k0 % CIN;
            const int*   id = bc_idx + ((size_t)v * (RR * AA) + ra) * 3;
            const float* w  = bc_w   + ((size_t)v * (RR * AA) + ra) * 3;
            int i0 = id[0] * CIN, i1 = id[1] * CIN, i2 = id[2] * CIN;
            float w0 = w[0], w1 = w[1], w2 = w[2];
#pragma unroll
            for (int e = 0; e < 4; ++e)
                s[e] = g_x[i0 + c0 + e] * w0 + g_x[i1 + c0 + e] * w1 +
                       g_x[i2 + c0 + e] * w2;
        } else {
#pragma unroll
            for (int e = 0; e < 4; ++e) {
                int k = k0 + e;
                if (k < K) {
                    int ra = k / CIN, c = k % CIN;
                    const int*   id = bc_idx + ((size_t)v * (RR * AA) + ra) * 3;
                    const float* w  = bc_w   + ((size_t)v * (RR * AA) + ra) * 3;
                    s[e] = g_x[id[0] * CIN + c] * w[0] +
                           g_x[id[1] * CIN + c] * w[1] +
                           g_x[id[2] * CIN + c] * w[2];
                }
            }
        }
    }
    store4(pa, (size_t)v * (2 * KPAD), k0, s);
}

template <int CIN, int KPAD>
__global__ void k_brot(const float* __restrict__ W,
                       __nv_bfloat16* __restrict__ bb) {
    constexpr int QK = KPAD / 4;
    constexpr int K = RR * AA * CIN;
    int i = blockIdx.x * blockDim.x + threadIdx.x;
    if (i >= NCONV * QK) return;
    int q = i % QK, col = i / QK;
    int k0 = q * 4;
    int t = col % TT, n = col / TT;
    float s[4] = {0.f, 0.f, 0.f, 0.f};
#pragma unroll
    for (int e = 0; e < 4; ++e) {
        int k = k0 + e;
        if (k < K) {
            int c = k % CIN, ra = k / CIN;
            int a = ra & (AA - 1), r = ra >> 3;
            int a2 = (a + n) & (AA - 1);
            s[e] = W[((t * RR + r) * AA + a2) * CIN + c];
        }
    }
    store4(bb, (size_t)col * (2 * KPAD), k0, s);
}

__global__ void k_xpad() {
    int i = blockIdx.x * blockDim.x + threadIdx.x;
    if (i >= V * 32) return;
    int v = i >> 5, k0 = (i & 31) * 4;
    float s[4];
#pragma unroll
    for (int e = 0; e < 4; ++e)
        s[e] = (k0 + e < TT) ? g_x[v * TT + k0 + e] : 0.f;
    store4(g_xx, (size_t)v * (2 * KPAD_S), k0, s);
}

__global__ void k_dwt(const float* __restrict__ dw) {
    int i = blockIdx.x * blockDim.x + threadIdx.x;
    if (i >= V * 32) return;
    int n = i >> 5, k0 = (i & 31) * 4;
    float s[4];
#pragma unroll
    for (int e = 0; e < 4; ++e)
        s[e] = (k0 + e < TT) ? dw[(size_t)(k0 + e) * V + n] : 0.f;
    store4(g_dd, (size_t)n * (2 * KPAD_S), k0, s);
}

// AMP: reduce NP split-K partials + bias, relu, first-max rotation, BN.
template <int NP>
__global__ void k_amp_bn(const float* __restrict__ bias,
                         const float* __restrict__ gam,
                         const float* __restrict__ bet,
                         const float* __restrict__ mu,
                         const float* __restrict__ var) {
    int warp = (blockIdx.x * blockDim.x + threadIdx.x) / 32;
    int lane = threadIdx.x & 31;
    if (warp >= V) return;
    const float* r0 = g_conv + (size_t)warp * NCONV;
    const size_t pstride = (size_t)V * NCONV;
    float best = -1.f;
    int bestn = 0;
#pragma unroll
    for (int n = 0; n < AA; ++n) {
        float s = 0.f;
        for (int t = lane; t < TT; t += 32) {
            float x = 0.f;
#pragma unroll
            for (int p = 0; p < NP; ++p) x += r0[p * pstride + n * TT + t];
            x = fmaxf(x + bias[t], 0.f);
            s += x * x;
        }
#pragma unroll
        for (int off = 16; off > 0; off >>= 1)
            s += __shfl_xor_sync(0xFFFFFFFFu, s, off);
        if (s > best) { best = s; bestn = n; }
    }
    for (int t = lane; t < TT; t += 32) {
        float x = 0.f;
#pragma unroll
        for (int p = 0; p < NP; ++p) x += r0[p * pstride + bestn * TT + t];
        x = fmaxf(x + bias[t], 0.f);
        g_x[warp * TT + t] = gam[t] * (x - mu[t]) * rsqrtf(var[t] + EPS_BN) + bet[t];
    }
}

// -------------------- HMMA GEMM: 4 warps, 64x64/warp, 3-stage --------------
#define STGB 32768
#define SMEM_BYTES (3 * STGB + 1024)

__device__ __forceinline__ void load_stage(
    uint32_t sm, const __nv_bfloat16* A2, const __nv_bfloat16* B2,
    int row0, int col0, int M, int N, size_t KP2, int chunk, int tid) {
#pragma unroll
    for (int tI = 0; tI < 2; ++tI) {
        const __nv_bfloat16* src = tI ? B2 : A2;
        int rb = tI ? col0 : row0;
        int rm = tI ? N : M;
#pragma unroll
        for (int it = 0; it < 8; ++it) {
            int idx = tid + it * 128;
            int row = idx >> 3, seg = idx & 7;
            int gr = rb + row;
            if (gr > rm - 1) gr = rm - 1;
            const void* g = src + (size_t)gr * KP2 + (size_t)chunk * 64 + seg * 8;
            uint32_t dst = sm + tI * 16384 + SWZ((uint32_t)(row * 128 + seg * 16));
            CP_ASYNC16(dst, g);
        }
    }
    CP_COMMIT();
}

// mode 0: raw partial to C + part*M*N. mode 1: C += bias[col] (dense head).
__global__ void __launch_bounds__(128, 2)
k_gemm(const __nv_bfloat16* __restrict__ A2, const __nv_bfloat16* __restrict__ B2,
       const float* __restrict__ bias, float* __restrict__ C,
       int M, int N, int Kpad, int mode, int chPer) {
    extern __shared__ char dsm[];
    uint32_t raw = smem_u32(dsm);
    uint32_t sbase = (raw + 1023u) & ~1023u;

    int tid = threadIdx.x, wid = tid >> 5, lane = tid & 31;
    int warp_m = wid & 1, warp_n = wid >> 1;
    int row0 = blockIdx.y * 128, col0 = blockIdx.x * 128;
    int part = blockIdx.z;
    int nchTot = Kpad >> 5;
    int kc0 = part * chPer;
    int kc1 = kc0 + chPer; if (kc1 > nchTot) kc1 = nchTot;
    float* Cp = C + (size_t)part * M * N;
    size_t KP2 = 2 * (size_t)Kpad;

    float acc[4][8][4];
#pragma unroll
    for (int i = 0; i < 4; ++i)
#pragma unroll
        for (int j = 0; j < 8; ++j)
#pragma unroll
            for (int q = 0; q < 4; ++q) acc[i][j][q] = 0.f;

    load_stage(sbase,        A2, B2, row0, col0, M, N, KP2, kc0, tid);
    load_stage(sbase + STGB, A2, B2, row0, col0, M, N, KP2, kc0 + 1, tid);

    int slot = 0;
    for (int c = kc0; c < kc1; ++c) {
        if (c + 1 < kc1) { CP_WAIT1(); } else { CP_WAIT0(); }
        __syncthreads();
        if (c + 2 < kc1) {
            int wslot = slot + 2; if (wslot >= 3) wslot -= 3;
            load_stage(sbase + wslot * STGB, A2, B2, row0, col0, M, N, KP2,
                       c + 2, tid);
        }
        uint32_t sa = sbase + slot * STGB;
        if (++slot == 3) slot = 0;

#pragma unroll
        for (int ks = 0; ks < 2; ++ks) {
            uint32_t ah[4][4], bh[4][4], t2[4][4];
            // --- load A-hi and B-hi ---
#pragma unroll
            for (int mi = 0; mi < 4; ++mi) {
                int arow = warp_m * 64 + mi * 16 + (lane & 15);
                uint32_t off = (uint32_t)(arow * 128 + ks * 64 + ((lane >> 4) << 4));
                LDSM4(ah[mi], sa + SWZ(off));
            }
#pragma unroll
            for (int bi = 0; bi < 4; ++bi) {
                int m = lane >> 3;
                int brow = warp_n * 64 + bi * 16 + ((m >> 1) << 3) + (lane & 7);
                uint32_t off = (uint32_t)(brow * 128 + ks * 64 + ((m & 1) << 4));
                LDSM4(bh[bi], sa + 16384 + SWZ(off));
            }
            // --- pass hh ---
#pragma unroll
            for (int mi = 0; mi < 4; ++mi)
#pragma unroll
                for (int ni = 0; ni < 8; ++ni)
                    mma16816(acc[mi][ni], ah[mi], &bh[ni >> 1][(ni & 1) * 2]);
            // --- load A-lo into t2, pass lh ---
#pragma unroll
            for (int mi = 0; mi < 4; ++mi) {
                int arow = warp_m * 64 + mi * 16 + (lane & 15);
                uint32_t off = (uint32_t)(arow * 128 + ks * 64 + ((lane >> 4) << 4));
                LDSM4(t2[mi], sa + SWZ(off + 32));
            }
#pragma unroll
            for (int mi = 0; mi < 4; ++mi)
#pragma unroll
                for (int ni = 0; ni < 8; ++ni)
                    mma16816(acc[mi][ni], t2[mi], &bh[ni >> 1][(ni & 1) * 2]);
            // --- load B-lo into t2 (A-lo dead), pass hl ---
#pragma unroll
            for (int bi = 0; bi < 4; ++bi) {
                int m = lane >> 3;
                int brow = warp_n * 64 + bi * 16 + ((m >> 1) << 3) + (lane & 7);
                uint32_t off = (uint32_t)(brow * 128 + ks * 64 + ((m & 1) << 4));
                LDSM4(t2[bi], sa + 16384 + SWZ(off + 32));
            }
#pragma unroll
            for (int mi = 0; mi < 4; ++mi)
#pragma unroll
                for (int ni = 0; ni < 8; ++ni)
                    mma16816(acc[mi][ni], ah[mi], &t2[ni >> 1][(ni & 1) * 2]);
        }
    }

    int rbase = row0 + warp_m * 64;
    int cbase = col0 + warp_n * 64;
#pragma unroll
    for (int mi = 0; mi < 4; ++mi)
#pragma unroll
        for (int ni = 0; ni < 8; ++ni) {
            int r = rbase + mi * 16 + (lane >> 2);
            int cc = cbase + ni * 8 + (lane & 3) * 2;
            if (cc < N) {
                float b0 = mode ? bias[cc] : 0.f;
                float b1 = mode ? bias[cc + 1] : 0.f;
                if (r < M)
                    *(float2*)&Cp[(size_t)r * N + cc] =
                        make_float2(acc[mi][ni][0] + b0, acc[mi][ni][1] + b1);
                if (r + 8 < M)
                    *(float2*)&Cp[(size_t)(r + 8) * N + cc] =
                        make_float2(acc[mi][ni][2] + b0, acc[mi][ni][3] + b1);
            }
        }
}

// -------------------- launch --------------------
extern "C" void kernel_launch(void* const* d_in, const int* in_sizes, int n_in,
                              void* d_out, int out_size) {
    const float* signal = (const float*)d_in[0];
    const int*   bc_idx = (const int*)d_in[1];
    const float* bc_w   = (const float*)d_in[2];
    const float* nmean  = (const float*)d_in[3];
    const float* nvar   = (const float*)d_in[4];
    const float* Ws[3]  = {(const float*)d_in[5], (const float*)d_in[7],
                           (const float*)d_in[9]};
    const float* Bls[3] = {(const float*)d_in[6], (const float*)d_in[8],
                           (const float*)d_in[10]};
    const float* bng = (const float*)d_in[11];
    const float* bnb = (const float*)d_in[12];
    const float* bnm = (const float*)d_in[13];
    const float* bnv = (const float*)d_in[14];
    const float* dw  = (const float*)d_in[15];
    const float* db  = (const float*)d_in[16];
    float* out = (float*)d_out;

    cudaFuncSetAttribute(k_gemm, cudaFuncAttributeMaxDynamicSharedMemorySize,
                         SMEM_BYTES);

    __nv_bfloat16 *pPA, *pBB, *pXX, *pDD;
    float *pConv;
    cudaGetSymbolAddress((void**)&pPA, g_pa);
    cudaGetSymbolAddress((void**)&pBB, g_bb);
    cudaGetSymbolAddress((void**)&pXX, g_xx);
    cudaGetSymbolAddress((void**)&pDD, g_dd);
    cudaGetSymbolAddress((void**)&pConv, g_conv);

    k_norm<<<(V * 3 + 255) / 256, 256>>>(signal, nmean, nvar);

    for (int l = 0; l < 3; ++l) {
        int Kpad = (l == 0) ? KPAD_S : KPAD_BIG;
        int nP = V * (Kpad / 4);
        int nB = NCONV * (Kpad / 4);
        if (l == 0) {
            k_patch<3, KPAD_S><<<(nP + 255) / 256, 256>>>(bc_idx, bc_w, pPA);
            k_brot<3, KPAD_S><<<(nB + 255) / 256, 256>>>(Ws[l], pBB);
            dim3 g((NCONV + 127) / 128, (V + 127) / 128, 2);   // split-K x2
            k_gemm<<<g, 128, SMEM_BYTES>>>(pPA, pBB, Bls[l], pConv,
                                           V, NCONV, Kpad, 0, 2);
            k_amp_bn<2><<<(V + 7) / 8, 256>>>(Bls[l], bng + l * TT, bnb + l * TT,
                                              bnm + l * TT, bnv + l * TT);
        } else {
            k_patch<TT, KPAD_BIG><<<(nP + 255) / 256, 256>>>(bc_idx, bc_w, pPA);
            k_brot<TT, KPAD_BIG><<<(nB + 255) / 256, 256>>>(Ws[l], pBB);
            dim3 g((NCONV + 127) / 128, (V + 127) / 128, 3);   // split-K x3
            k_gemm<<<g, 128, SMEM_BYTES>>>(pPA, pBB, Bls[l], pConv,
                                           V, NCONV, Kpad, 0, 42);
            k_amp_bn<3><<<(V + 7) / 8, 256>>>(Bls[l], bng + l * TT, bnb + l * TT,
                                              bnm + l * TT, bnv + l * TT);
        }
    }

    k_xpad<<<(V * 32 + 255) / 256, 256>>>();
    k_dwt<<<(V * 32 + 255) / 256, 256>>>(dw);
    dim3 g2((V + 127) / 128, (V + 127) / 128, 1);
    k_gemm<<<g2, 128, SMEM_BYTES>>>(pXX, pDD, db, out, V, V, KPAD_S, 1, 4);
}

// round 9
// speedup vs baseline: 1.0042x; 1.0042x over previous
#include <cuda_runtime.h>
#include <cuda_bf16.h>
#include <cstdint>

// ---------------------------------------------------------------------------
// IMCNN forward. HMMA m16n8k16 bf16, bf16x3 split, fp32 accum.
// R9: R7 inner loop restored (independent fragment loads, no WAR
//     serialization); split-K x3 on big layers only (wave quant 1.17->1.045);
//     layer-0 back to z=1; k_norm fused into layer-0 patch.
// ---------------------------------------------------------------------------

#define V      6890
#define RR     5
#define AA     8
#define TT     100
#define NCONV  800
#define KPAD_BIG 4032
#define KPAD_S   128
#define EPS_BN 1e-3f

__device__ float g_x[V * TT];
__device__ float g_conv[3 * V * NCONV];        // up to 3 split-K partials
__device__ __align__(16) __nv_bfloat16 g_pa[(size_t)V * 2 * KPAD_BIG];
__device__ __align__(16) __nv_bfloat16 g_bb[(size_t)NCONV * 2 * KPAD_BIG];
__device__ __align__(16) __nv_bfloat16 g_xx[(size_t)V * 2 * KPAD_S];
__device__ __align__(16) __nv_bfloat16 g_dd[(size_t)V * 2 * KPAD_S];

// -------------------- PTX helpers --------------------
__device__ __forceinline__ uint32_t smem_u32(const void* p) {
    uint32_t a;
    asm("{ .reg .u64 t; cvta.to.shared.u64 t, %1; cvt.u32.u64 %0, t; }"
        : "=r"(a) : "l"(p));
    return a;
}
#define CP_ASYNC16(dst, src) \
    asm volatile("cp.async.cg.shared.global [%0], [%1], 16;" \
                 :: "r"(dst), "l"(src))
#define CP_COMMIT() asm volatile("cp.async.commit_group;" ::: "memory")
#define CP_WAIT1()  asm volatile("cp.async.wait_group 1;" ::: "memory")
#define CP_WAIT0()  asm volatile("cp.async.wait_group 0;" ::: "memory")

#define LDSM4(R, addr) \
    asm volatile("ldmatrix.sync.aligned.m8n8.x4.shared.b16 {%0,%1,%2,%3}, [%4];" \
        : "=r"((R)[0]), "=r"((R)[1]), "=r"((R)[2]), "=r"((R)[3]) : "r"(addr))

#define SWZ(o) ((o) ^ (((o) >> 3) & 0x70))

__device__ __forceinline__ void mma16816(float* c, const uint32_t* a,
                                         const uint32_t* b) {
    asm volatile(
        "mma.sync.aligned.m16n8k16.row.col.f32.bf16.bf16.f32 "
        "{%0,%1,%2,%3}, {%4,%5,%6,%7}, {%8,%9}, {%0,%1,%2,%3};"
        : "+f"(c[0]), "+f"(c[1]), "+f"(c[2]), "+f"(c[3])
        : "r"(a[0]), "r"(a[1]), "r"(a[2]), "r"(a[3]), "r"(b[0]), "r"(b[1]));
}

// -------------------- small kernels --------------------
__device__ __forceinline__ void store4(__nv_bfloat16* buf, size_t rowbase,
                                       int k0, const float* s) {
    int kb = k0 >> 4, pos = k0 & 15;
    __nv_bfloat16 hv[4], lv[4];
#pragma unroll
    for (int e = 0; e < 4; ++e) {
        hv[e] = __float2bfloat16_rn(s[e]);
        lv[e] = __float2bfloat16_rn(s[e] - __bfloat162float(hv[e]));
    }
    size_t base = rowbase + (size_t)(kb * 32 + pos);
    *(uint2*)(buf + base)      = *(const uint2*)hv;
    *(uint2*)(buf + base + 16) = *(const uint2*)lv;
}

// layer-0 patch: normalization fused (reads raw signal, mean, var)
__global__ void k_patch0(const int* __restrict__ bc_idx,
                         const float* __restrict__ bc_w,
                         const float* __restrict__ sig,
                         const float* __restrict__ mean,
                         const float* __restrict__ var,
                         __nv_bfloat16* __restrict__ pa) {
    constexpr int CIN = 3;
    constexpr int KPAD = KPAD_S;
    constexpr int QK = KPAD / 4;
    constexpr int K = RR * AA * CIN;
    int i = blockIdx.x * blockDim.x + threadIdx.x;
    if (i >= V * QK) return;
    int q = i % QK, v = i / QK;
    int k0 = q * 4;
    float s[4] = {0.f, 0.f, 0.f, 0.f};
#pragma unroll
    for (int e = 0; e < 4; ++e) {
        int k = k0 + e;
        if (k < K) {
            int ra = k / CIN, c = k % CIN;
            const int*   id = bc_idx + ((size_t)v * (RR * AA) + ra) * 3;
            const float* w  = bc_w   + ((size_t)v * (RR * AA) + ra) * 3;
            float inv = rsqrtf(var[c]);
            float m = mean[c];
            s[e] = (sig[id[0] * CIN + c] - m) * inv * w[0] +
                   (sig[id[1] * CIN + c] - m) * inv * w[1] +
                   (sig[id[2] * CIN + c] - m) * inv * w[2];
        }
    }
    store4(pa, (size_t)v * (2 * KPAD), k0, s);
}

template <int CIN, int KPAD>
__global__ void k_patch(const int* __restrict__ bc_idx,
                        const float* __restrict__ bc_w,
                        __nv_bfloat16* __restrict__ pa) {
    constexpr int QK = KPAD / 4;
    constexpr int K = RR * AA * CIN;
    int i = blockIdx.x * blockDim.x + threadIdx.x;
    if (i >= V * QK) return;
    int q = i % QK, v = i / QK;
    int k0 = q * 4;
    float s[4] = {0.f, 0.f, 0.f, 0.f};
    if (k0 < K) {
        int ra = k0 / CIN, c0 = k0 % CIN;
        const int*   id = bc_idx + ((size_t)v * (RR * AA) + ra) * 3;
        const float* w  = bc_w   + ((size_t)v * (RR * AA) + ra) * 3;
        int i0 = id[0] * CIN, i1 = id[1] * CIN, i2 = id[2] * CIN;
        float w0 = w[0], w1 = w[1], w2 = w[2];
#pragma unroll
        for (int e = 0; e < 4; ++e)
            s[e] = g_x[i0 + c0 + e] * w0 + g_x[i1 + c0 + e] * w1 +
                   g_x[i2 + c0 + e] * w2;
    }
    store4(pa, (size_t)v * (2 * KPAD), k0, s);
}

template <int CIN, int KPAD>
__global__ void k_brot(const float* __restrict__ W,
                       __nv_bfloat16* __restrict__ bb) {
    constexpr int QK = KPAD / 4;
    constexpr int K = RR * AA * CIN;
    int i = blockIdx.x * blockDim.x + threadIdx.x;
    if (i >= NCONV * QK) return;
    int q = i % QK, col = i / QK;
    int k0 = q * 4;
    int t = col % TT, n = col / TT;
    float s[4] = {0.f, 0.f, 0.f, 0.f};
#pragma unroll
    for (int e = 0; e < 4; ++e) {
        int k = k0 + e;
        if (k < K) {
            int c = k % CIN, ra = k / CIN;
            int a = ra & (AA - 1), r = ra >> 3;
            int a2 = (a + n) & (AA - 1);
            s[e] = W[((t * RR + r) * AA + a2) * CIN + c];
        }
    }
    store4(bb, (size_t)col * (2 * KPAD), k0, s);
}

__global__ void k_xpad() {
    int i = blockIdx.x * blockDim.x + threadIdx.x;
    if (i >= V * 32) return;
    int v = i >> 5, k0 = (i & 31) * 4;
    float s[4];
#pragma unroll
    for (int e = 0; e < 4; ++e)
        s[e] = (k0 + e < TT) ? g_x[v * TT + k0 + e] : 0.f;
    store4(g_xx, (size_t)v * (2 * KPAD_S), k0, s);
}

__global__ void k_dwt(const float* __restrict__ dw) {
    int i = blockIdx.x * blockDim.x + threadIdx.x;
    if (i >= V * 32) return;
    int n = i >> 5, k0 = (i & 31) * 4;
    float s[4];
#pragma unroll
    for (int e = 0; e < 4; ++e)
        s[e] = (k0 + e < TT) ? dw[(size_t)(k0 + e) * V + n] : 0.f;
    store4(g_dd, (size_t)n * (2 * KPAD_S), k0, s);
}

// AMP: reduce NP split-K partials + bias, relu, first-max rotation, BN.
template <int NP>
__global__ void k_amp_bn(const float* __restrict__ bias,
                         const float* __restrict__ gam,
                         const float* __restrict__ bet,
                         const float* __restrict__ mu,
                         const float* __restrict__ var) {
    int warp = (blockIdx.x * blockDim.x + threadIdx.x) / 32;
    int lane = threadIdx.x & 31;
    if (warp >= V) return;
    const float* r0 = g_conv + (size_t)warp * NCONV;
    const size_t pstride = (size_t)V * NCONV;
    float best = -1.f;
    int bestn = 0;
#pragma unroll
    for (int n = 0; n < AA; ++n) {
        float s = 0.f;
        for (int t = lane; t < TT; t += 32) {
            float x = 0.f;
#pragma unroll
            for (int p = 0; p < NP; ++p) x += r0[p * pstride + n * TT + t];
            x = fmaxf(x + bias[t], 0.f);
            s += x * x;
        }
#pragma unroll
        for (int off = 16; off > 0; off >>= 1)
            s += __shfl_xor_sync(0xFFFFFFFFu, s, off);
        if (s > best) { best = s; bestn = n; }
    }
    for (int t = lane; t < TT; t += 32) {
        float x = 0.f;
#pragma unroll
        for (int p = 0; p < NP; ++p) x += r0[p * pstride + bestn * TT + t];
        x = fmaxf(x + bias[t], 0.f);
        g_x[warp * TT + t] = gam[t] * (x - mu[t]) * rsqrtf(var[t] + EPS_BN) + bet[t];
    }
}

// -------------------- HMMA GEMM: 4 warps, 64x64/warp, 3-stage --------------
#define STGB 32768
#define SMEM_BYTES (3 * STGB + 1024)

__device__ __forceinline__ void load_stage(
    uint32_t sm, const __nv_bfloat16* A2, const __nv_bfloat16* B2,
    int row0, int col0, int M, int N, size_t KP2, int chunk, int tid) {
#pragma unroll
    for (int tI = 0; tI < 2; ++tI) {
        const __nv_bfloat16* src = tI ? B2 : A2;
        int rb = tI ? col0 : row0;
        int rm = tI ? N : M;
#pragma unroll
        for (int it = 0; it < 8; ++it) {
            int idx = tid + it * 128;
            int row = idx >> 3, seg = idx & 7;
            int gr = rb + row;
            if (gr > rm - 1) gr = rm - 1;
            const void* g = src + (size_t)gr * KP2 + (size_t)chunk * 64 + seg * 8;
            uint32_t dst = sm + tI * 16384 + SWZ((uint32_t)(row * 128 + seg * 16));
            CP_ASYNC16(dst, g);
        }
    }
    CP_COMMIT();
}

// mode 0: raw partial to C + part*M*N. mode 1: C += bias[col] (dense head).
__global__ void __launch_bounds__(128, 2)
k_gemm(const __nv_bfloat16* __restrict__ A2, const __nv_bfloat16* __restrict__ B2,
       const float* __restrict__ bias, float* __restrict__ C,
       int M, int N, int Kpad, int mode, int chPer) {
    extern __shared__ char dsm[];
    uint32_t raw = smem_u32(dsm);
    uint32_t sbase = (raw + 1023u) & ~1023u;

    int tid = threadIdx.x, wid = tid >> 5, lane = tid & 31;
    int warp_m = wid & 1, warp_n = wid >> 1;
    int row0 = blockIdx.y * 128, col0 = blockIdx.x * 128;
    int part = blockIdx.z;
    int nchTot = Kpad >> 5;
    int kc0 = part * chPer;
    int kc1 = kc0 + chPer; if (kc1 > nchTot) kc1 = nchTot;
    float* Cp = C + (size_t)part * M * N;
    size_t KP2 = 2 * (size_t)Kpad;

    float acc[4][8][4];
#pragma unroll
    for (int i = 0; i < 4; ++i)
#pragma unroll
        for (int j = 0; j < 8; ++j)
#pragma unroll
            for (int q = 0; q < 4; ++q) acc[i][j][q] = 0.f;

    load_stage(sbase,        A2, B2, row0, col0, M, N, KP2, kc0, tid);
    load_stage(sbase + STGB, A2, B2, row0, col0, M, N, KP2, kc0 + 1, tid);

    int slot = 0;
    for (int c = kc0; c < kc1; ++c) {
        if (c + 1 < kc1) { CP_WAIT1(); } else { CP_WAIT0(); }
        __syncthreads();
        if (c + 2 < kc1) {
            int wslot = slot + 2; if (wslot >= 3) wslot -= 3;
            load_stage(sbase + wslot * STGB, A2, B2, row0, col0, M, N, KP2,
                       c + 2, tid);
        }
        uint32_t sa = sbase + slot * STGB;
        if (++slot == 3) slot = 0;

#pragma unroll
        for (int ks = 0; ks < 2; ++ks) {
            uint32_t ah[4][4], al[4][4], bh[4][4], bl[4][4];
#pragma unroll
            for (int mi = 0; mi < 4; ++mi) {
                int arow = warp_m * 64 + mi * 16 + (lane & 15);
                uint32_t off = (uint32_t)(arow * 128 + ks * 64 + ((lane >> 4) << 4));
                LDSM4(ah[mi], sa + SWZ(off));
                LDSM4(al[mi], sa + SWZ(off + 32));
            }
#pragma unroll
            for (int bi = 0; bi < 4; ++bi) {
                int m = lane >> 3;
                int brow = warp_n * 64 + bi * 16 + ((m >> 1) << 3) + (lane & 7);
                uint32_t off = (uint32_t)(brow * 128 + ks * 64 + ((m & 1) << 4));
                LDSM4(bh[bi], sa + 16384 + SWZ(off));
                LDSM4(bl[bi], sa + 16384 + SWZ(off + 32));
            }
            // pass-major: 32 independent MMAs between accumulator reuses
#pragma unroll
            for (int mi = 0; mi < 4; ++mi)
#pragma unroll
                for (int ni = 0; ni < 8; ++ni)
                    mma16816(acc[mi][ni], ah[mi], &bh[ni >> 1][(ni & 1) * 2]);
#pragma unroll
            for (int mi = 0; mi < 4; ++mi)
#pragma unroll
                for (int ni = 0; ni < 8; ++ni)
                    mma16816(acc[mi][ni], ah[mi], &bl[ni >> 1][(ni & 1) * 2]);
#pragma unroll
            for (int mi = 0; mi < 4; ++mi)
#pragma unroll
                for (int ni = 0; ni < 8; ++ni)
                    mma16816(acc[mi][ni], al[mi], &bh[ni >> 1][(ni & 1) * 2]);
        }
    }

    int rbase = row0 + warp_m * 64;
    int cbase = col0 + warp_n * 64;
#pragma unroll
    for (int mi = 0; mi < 4; ++mi)
#pragma unroll
        for (int ni = 0; ni < 8; ++ni) {
            int r = rbase + mi * 16 + (lane >> 2);
            int cc = cbase + ni * 8 + (lane & 3) * 2;
            if (cc < N) {
                float b0 = mode ? bias[cc] : 0.f;
                float b1 = mode ? bias[cc + 1] : 0.f;
                if (r < M)
                    *(float2*)&Cp[(size_t)r * N + cc] =
                        make_float2(acc[mi][ni][0] + b0, acc[mi][ni][1] + b1);
                if (r + 8 < M)
                    *(float2*)&Cp[(size_t)(r + 8) * N + cc] =
                        make_float2(acc[mi][ni][2] + b0, acc[mi][ni][3] + b1);
            }
        }
}

// -------------------- launch --------------------
extern "C" void kernel_launch(void* const* d_in, const int* in_sizes, int n_in,
                              void* d_out, int out_size) {
    const float* signal = (const float*)d_in[0];
    const int*   bc_idx = (const int*)d_in[1];
    const float* bc_w   = (const float*)d_in[2];
    const float* nmean  = (const float*)d_in[3];
    const float* nvar   = (const float*)d_in[4];
    const float* Ws[3]  = {(const float*)d_in[5], (const float*)d_in[7],
                           (const float*)d_in[9]};
    const float* Bls[3] = {(const float*)d_in[6], (const float*)d_in[8],
                           (const float*)d_in[10]};
    const float* bng = (const float*)d_in[11];
    const float* bnb = (const float*)d_in[12];
    const float* bnm = (const float*)d_in[13];
    const float* bnv = (const float*)d_in[14];
    const float* dw  = (const float*)d_in[15];
    const float* db  = (const float*)d_in[16];
    float* out = (float*)d_out;

    cudaFuncSetAttribute(k_gemm, cudaFuncAttributeMaxDynamicSharedMemorySize,
                         SMEM_BYTES);

    __nv_bfloat16 *pPA, *pBB, *pXX, *pDD;
    float *pConv;
    cudaGetSymbolAddress((void**)&pPA, g_pa);
    cudaGetSymbolAddress((void**)&pBB, g_bb);
    cudaGetSymbolAddress((void**)&pXX, g_xx);
    cudaGetSymbolAddress((void**)&pDD, g_dd);
    cudaGetSymbolAddress((void**)&pConv, g_conv);

    for (int l = 0; l < 3; ++l) {
        int Kpad = (l == 0) ? KPAD_S : KPAD_BIG;
        int nP = V * (Kpad / 4);
        int nB = NCONV * (Kpad / 4);
        if (l == 0) {
            k_patch0<<<(nP + 255) / 256, 256>>>(bc_idx, bc_w, signal,
                                                nmean, nvar, pPA);
            k_brot<3, KPAD_S><<<(nB + 255) / 256, 256>>>(Ws[l], pBB);
            dim3 g((NCONV + 127) / 128, (V + 127) / 128, 1);
            k_gemm<<<g, 128, SMEM_BYTES>>>(pPA, pBB, Bls[l], pConv,
                                           V, NCONV, Kpad, 0, 4);
            k_amp_bn<1><<<(V + 7) / 8, 256>>>(Bls[l], bng + l * TT, bnb + l * TT,
                                              bnm + l * TT, bnv + l * TT);
        } else {
            k_patch<TT, KPAD_BIG><<<(nP + 255) / 256, 256>>>(bc_idx, bc_w, pPA);
            k_brot<TT, KPAD_BIG><<<(nB + 255) / 256, 256>>>(Ws[l], pBB);
            dim3 g((NCONV + 127) / 128, (V + 127) / 128, 3);   // split-K x3
            k_gemm<<<g, 128, SMEM_BYTES>>>(pPA, pBB, Bls[l], pConv,
                                           V, NCONV, Kpad, 0, 42);
            k_amp_bn<3><<<(V + 7) / 8, 256>>>(Bls[l], bng + l * TT, bnb + l * TT,
                                              bnm + l * TT, bnv + l * TT);
        }
    }

    k_xpad<<<(V * 32 + 255) / 256, 256>>>();
    k_dwt<<<(V * 32 + 255) / 256, 256>>>(dw);
    dim3 g2((V + 127) / 128, (V + 127) / 128, 1);
    k_gemm<<<g2, 128, SMEM_BYTES>>>(pXX, pDD, db, out, V, V, KPAD_S, 1, 4);
}